// round 7
// baseline (speedup 1.0000x reference)
#include <cuda_runtime.h>

// SNN recurrence: B=1024, T=1024, H=32, I=2.
// One warp per batch, one lane per hidden unit, scalar fp32, bit-exact
// reference-order arithmetic (proven rel_err = 0.0).
// R7 changes:
//  - spike = FSET (set.gt.f32.f32 -> 1.0f/0.0f in ONE instruction) instead of
//    FSETP+FSEL; soma input m = FMUL(bs, s) (bit-exact: bs*1=bs, bs*0=+0).
//  - input term u = bg*(x0*w0+x1*w1) pipelined TWO steps ahead so the 29-cyc
//    LDS latency is fully hidden; boundary steps statically read the first two
//    entries of the next chunk's buffer (no branches in the inner loop).

#define TT 1024

__device__ __forceinline__ float fset_gt1(float v) {
    float r;
    asm("set.gt.f32.f32 %0, %1, 0f3F800000;" : "=f"(r) : "f"(v));
    return r;  // (v > 1.0f) ? 1.0f : 0.0f
}

__device__ __forceinline__ float uterm(float2 xv, float w0, float w1, float bg) {
    // bg*(x0*w0 + x1*w1), reference rounding order
    return __fmul_rn(bg, __fadd_rn(__fmul_rn(xv.x, w0), __fmul_rn(xv.y, w1)));
}

template <bool ACC>
__device__ __forceinline__ void run32(const float2* __restrict__ buf,
                                      const float2* __restrict__ bufnext,
                                      float& v, float& s, float& V, float& S,
                                      float& acc,
                                      float w0, float w1, float ag, float bg,
                                      float as, float bs)
{
    // Prime u pipeline (depth 2): LDS latency exposed only here, once per chunk
    float u0 = uterm(buf[0], w0, w1, bg);
    float u1 = uterm(buf[1], w0, w1, bg);

    #pragma unroll
    for (int i = 0; i < 32; ++i) {
        // Prefetch u_{i+2}: static boundary select, no runtime branch
        float2 xn = (i + 2 < 32) ? buf[i + 2] : bufnext[i + 2 - 32];
        float un = uterm(xn, w0, w1, bg);

        // v = (ag*v + u) - s   (reference order, single-rounded each op)
        v = __fsub_rn(__fadd_rn(__fmul_rn(ag, v), u0), s);
        s = fset_gt1(v);                       // 1.0 / 0.0
        const float m = __fmul_rn(bs, s);      // bs or +0, exact

        // V = (as*V + m) - S
        V = __fsub_rn(__fadd_rn(__fmul_rn(as, V), m), S);
        S = fset_gt1(V);

        if (ACC) acc = __fadd_rn(acc, S);

        u0 = u1;
        u1 = un;
    }
}

__global__ __launch_bounds__(256, 1)
void snn_kernel(const float* __restrict__ x,
                const float* __restrict__ Wg,     // [32,2]
                const float* __restrict__ tau_g,  // [32]
                const float* __restrict__ tau_s,  // [32]
                const float* __restrict__ Wout,   // [32]
                const float* __restrict__ bout,   // [1]
                float* __restrict__ out)          // [1024]
{
    const int lane = threadIdx.x & 31;
    const int wib  = threadIdx.x >> 5;
    const int b    = blockIdx.x * 8 + wib;

    __shared__ float2 sbuf[8][2][32];   // [warp-in-block][double buffer][step]

    const float w0 = Wg[2 * lane];
    const float w1 = Wg[2 * lane + 1];
    const float ag = 1.0f / (1.0f + expf(-tau_g[lane]));
    const float bg = 1.0f - ag;
    const float as = 1.0f / (1.0f + expf(-tau_s[lane]));
    const float bs = 1.0f - as;

    const float2* xp = reinterpret_cast<const float2*>(x) + (size_t)b * TT;

    float v = 0.0f, s = 0.0f, V = 0.0f, S = 0.0f, acc = 0.0f;

    // Prime BOTH buffers: chunk 0 -> buf0, chunk 1 -> buf1
    sbuf[wib][0][lane] = xp[lane];
    sbuf[wib][1][lane] = xp[32 + lane];
    __syncwarp();
    int cur = 0;

    // Invariant at chunk c: buf[cur] = chunk c, buf[cur^1] = chunk c+1.
    // After run32(c), STS chunk c+2 into buf[cur] (its first 2 entries are the
    // cross-boundary prefetch targets of run32(c+1)).
    #pragma unroll 1
    for (int chunk = 0; chunk < 24; ++chunk) {
        float2 nxt;
        if (chunk < 30) nxt = xp[(chunk + 2) * 32 + lane];
        run32<false>(sbuf[wib][cur], sbuf[wib][cur ^ 1],
                     v, s, V, S, acc, w0, w1, ag, bg, as, bs);
        if (chunk < 30) sbuf[wib][cur][lane] = nxt;
        __syncwarp();
        cur ^= 1;
    }
    #pragma unroll 1
    for (int chunk = 24; chunk < 32; ++chunk) {
        float2 nxt;
        if (chunk < 30) nxt = xp[(chunk + 2) * 32 + lane];
        run32<true>(sbuf[wib][cur], sbuf[wib][cur ^ 1],
                    v, s, V, S, acc, w0, w1, ag, bg, as, bs);
        if (chunk < 30) sbuf[wib][cur][lane] = nxt;
        __syncwarp();
        cur ^= 1;
    }

    // out[b] = sum_h acc_h * Wout[h] + bout  (same reduction tree as before)
    float val = __fmul_rn(acc, Wout[lane]);
    #pragma unroll
    for (int off = 16; off; off >>= 1)
        val += __shfl_xor_sync(0xffffffffu, val, off);
    if (lane == 0) out[b] = val + bout[0];
}

extern "C" void kernel_launch(void* const* d_in, const int* in_sizes, int n_in,
                              void* d_out, int out_size) {
    const float* x    = (const float*)d_in[0];
    const float* Wg   = (const float*)d_in[1];
    const float* taug = (const float*)d_in[2];
    const float* taus = (const float*)d_in[3];
    const float* Wout = (const float*)d_in[4];
    const float* bout = (const float*)d_in[5];
    float* out = (float*)d_out;

    // 1024 warps, uniform 2 warps/SMSP: 128 blocks x 256 threads
    snn_kernel<<<128, 256>>>(x, Wg, taug, taus, Wout, bout, out);
}

// round 8
// speedup vs baseline: 1.7790x; 1.7790x over previous
#include <cuda_runtime.h>

// SNN recurrence: B=1024, T=1024, H=32, I=2.
// One warp per batch, one lane per hidden unit, scalar fp32, bit-exact
// reference-order rounding (rel_err has been 0.0 for this sequence).
// R8: fully predicated inner step in ONE inline-PTX block per iteration —
// no FSELs, no branches. Predicates are produced and consumed inside the
// block (spike predicates recomputed from the carried v/V at block top, so
// nothing crosses the asm boundary). Spike resets are predicated adds of -1
// (bit-exact vs subtracting s in {0,1}); soma injection is a predicated add
// of bs (zero-sign-only divergence, provably invisible to spikes/output).
// Spike count is a predicated integer add (exact).

#define TT 1024

__device__ __forceinline__ float uterm(float2 xv, float w0, float w1, float bg) {
    // bg*(x0*w0 + x1*w1), reference rounding order
    return __fmul_rn(bg, __fadd_rn(__fmul_rn(xv.x, w0), __fmul_rn(xv.y, w1)));
}

__device__ __forceinline__ void step_plain(float& v, float& V, float u,
                                           float ag, float as, float bs) {
    asm("{\n\t"
        ".reg .pred p, q;\n\t"
        "setp.gt.f32 p, %0, 0f3F800000;\n\t"   // s_{t-1} = v_{t-1} > 1
        "setp.gt.f32 q, %1, 0f3F800000;\n\t"   // S_{t-1} = V_{t-1} > 1
        "mul.rn.f32 %0, %0, %3;\n\t"           // v = ag*v
        "add.rn.f32 %0, %0, %2;\n\t"           // v += u
        "@p add.rn.f32 %0, %0, 0fBF800000;\n\t"// v -= 1   (reset)
        "setp.gt.f32 p, %0, 0f3F800000;\n\t"   // s_t = v_t > 1
        "mul.rn.f32 %1, %1, %4;\n\t"           // V = as*V
        "@p add.rn.f32 %1, %1, %5;\n\t"        // V += bs  (injection)
        "@q add.rn.f32 %1, %1, 0fBF800000;\n\t"// V -= 1   (reset)
        "}"
        : "+f"(v), "+f"(V)
        : "f"(u), "f"(ag), "f"(as), "f"(bs));
}

__device__ __forceinline__ void step_acc(float& v, float& V, int& acc, float u,
                                         float ag, float as, float bs) {
    asm("{\n\t"
        ".reg .pred p, q;\n\t"
        "setp.gt.f32 p, %0, 0f3F800000;\n\t"
        "setp.gt.f32 q, %1, 0f3F800000;\n\t"
        "mul.rn.f32 %0, %0, %4;\n\t"
        "add.rn.f32 %0, %0, %3;\n\t"
        "@p add.rn.f32 %0, %0, 0fBF800000;\n\t"
        "setp.gt.f32 p, %0, 0f3F800000;\n\t"
        "mul.rn.f32 %1, %1, %5;\n\t"
        "@p add.rn.f32 %1, %1, %6;\n\t"
        "@q add.rn.f32 %1, %1, 0fBF800000;\n\t"
        "setp.gt.f32 q, %1, 0f3F800000;\n\t"   // S_t
        "@q add.s32 %2, %2, 1;\n\t"            // spike count (alu pipe, exact)
        "}"
        : "+f"(v), "+f"(V), "+r"(acc)
        : "f"(u), "f"(ag), "f"(as), "f"(bs));
}

template <bool ACC>
__device__ __forceinline__ void run32(const float2* __restrict__ buf,
                                      float& v, float& V, int& acc,
                                      float w0, float w1, float ag, float bg,
                                      float as, float bs)
{
    float u = uterm(buf[0], w0, w1, bg);   // LDS exposed once per chunk
    #pragma unroll
    for (int i = 0; i < 32; ++i) {
        float un = 0.0f;
        if (i < 31) un = uterm(buf[i + 1], w0, w1, bg);  // off-chain prefetch
        if (ACC) step_acc(v, V, acc, u, ag, as, bs);
        else     step_plain(v, V, u, ag, as, bs);
        u = un;
    }
}

__global__ __launch_bounds__(256, 1)
void snn_kernel(const float* __restrict__ x,
                const float* __restrict__ Wg,     // [32,2]
                const float* __restrict__ tau_g,  // [32]
                const float* __restrict__ tau_s,  // [32]
                const float* __restrict__ Wout,   // [32]
                const float* __restrict__ bout,   // [1]
                float* __restrict__ out)          // [1024]
{
    const int lane = threadIdx.x & 31;
    const int wib  = threadIdx.x >> 5;
    const int b    = blockIdx.x * 8 + wib;

    __shared__ float2 sbuf[8][2][32];   // [warp-in-block][double buffer][step]

    const float w0 = Wg[2 * lane];
    const float w1 = Wg[2 * lane + 1];
    const float ag = 1.0f / (1.0f + expf(-tau_g[lane]));
    const float bg = 1.0f - ag;
    const float as = 1.0f / (1.0f + expf(-tau_s[lane]));
    const float bs = 1.0f - as;

    const float2* xp = reinterpret_cast<const float2*>(x) + (size_t)b * TT;

    float v = 0.0f, V = 0.0f;
    int acc = 0;

    // Prime buffer 0
    float2 nxt = xp[lane];
    sbuf[wib][0][lane] = nxt;
    __syncwarp();
    int cur = 0;

    #pragma unroll 1
    for (int chunk = 0; chunk < 24; ++chunk) {
        nxt = xp[(chunk + 1) * 32 + lane];          // GMEM prefetch next chunk
        run32<false>(sbuf[wib][cur], v, V, acc, w0, w1, ag, bg, as, bs);
        sbuf[wib][cur ^ 1][lane] = nxt;
        __syncwarp();
        cur ^= 1;
    }
    #pragma unroll 1
    for (int chunk = 24; chunk < 32; ++chunk) {
        if (chunk + 1 < 32) nxt = xp[(chunk + 1) * 32 + lane];
        run32<true>(sbuf[wib][cur], v, V, acc, w0, w1, ag, bg, as, bs);
        if (chunk + 1 < 32) sbuf[wib][cur ^ 1][lane] = nxt;
        __syncwarp();
        cur ^= 1;
    }

    // out[b] = sum_h acc_h * Wout[h] + bout
    // (float)acc is the exact same value the previous rel_err=0.0 kernels
    // carried in float; identical butterfly reduction tree.
    float val = __fmul_rn((float)acc, Wout[lane]);
    #pragma unroll
    for (int off = 16; off; off >>= 1)
        val += __shfl_xor_sync(0xffffffffu, val, off);
    if (lane == 0) out[b] = val + bout[0];
}

extern "C" void kernel_launch(void* const* d_in, const int* in_sizes, int n_in,
                              void* d_out, int out_size) {
    const float* x    = (const float*)d_in[0];
    const float* Wg   = (const float*)d_in[1];
    const float* taug = (const float*)d_in[2];
    const float* taus = (const float*)d_in[3];
    const float* Wout = (const float*)d_in[4];
    const float* bout = (const float*)d_in[5];
    float* out = (float*)d_out;

    // 1024 warps, uniform 2 warps/SMSP on 128 SMs: 128 blocks x 256 threads
    snn_kernel<<<128, 256>>>(x, Wg, taug, taus, Wout, bout, out);
}